// round 2
// baseline (speedup 1.0000x reference)
#include <cuda_runtime.h>

#define BB 16
#define QQ 300
#define SNUM 16
#define HID 256
#define T_TOT 13125
#define W0 100
#define H0 100
#define QP 3
#define S_SCALE_C 0.077f

// scratch: pre-scaled tanh offsets for the 768 distinct (b, q', s) rows, 4 values each
__device__ float g_off[BB * QP * SNUM * 4];

// Kernel 1: bilinear sample level-0 features at the 768 distinct rows, run the MLP head.
__global__ void sample_mlp_kernel(const float* __restrict__ rp,
                                  const float* __restrict__ mem,
                                  const float* __restrict__ w1,
                                  const float* __restrict__ b1,
                                  const float* __restrict__ w2,
                                  const float* __restrict__ b2) {
    int blk = blockIdx.x;              // b*QP*SNUM + qp*SNUM + s
    int s  = blk % SNUM;
    int qp = (blk / SNUM) % QP;
    int b  = blk / (SNUM * QP);
    int tid = threadIdx.x;             // channel 0..255

    __shared__ float gs[HID];
    __shared__ float h1s[HID];

    // sampling location from cubic polynomial (queries 0..2 only)
    const float* rpq = rp + ((size_t)b * QQ + qp) * 8;
    float t  = (float)s * (1.0f / (float)(SNUM - 1));
    float t2 = t * t, t3 = t2 * t;
    float gx = 2.0f * (rpq[0] * t3 + rpq[1] * t2 + rpq[2] * t + rpq[3] - 0.5f);
    float gy = 2.0f * (rpq[4] * t3 + rpq[5] * t2 + rpq[6] * t + rpq[7] - 0.5f);
    float x = (gx + 1.0f) * (W0 * 0.5f) - 0.5f;
    float y = (gy + 1.0f) * (H0 * 0.5f) - 0.5f;
    float x0f = floorf(x), y0f = floorf(y);
    int x0 = (int)x0f, y0 = (int)y0f;
    float wx1 = x - x0f, wx0 = 1.0f - wx1;
    float wy1 = y - y0f, wy0 = 1.0f - wy1;

    // bilinear gather, zero padding (level 0 starts at memory offset 0)
    const float* memb = mem + (size_t)b * T_TOT * HID;
    float acc = 0.0f;
    #pragma unroll
    for (int dy = 0; dy < 2; dy++) {
        int yi = y0 + dy;
        float wy = dy ? wy1 : wy0;
        if (yi < 0 || yi >= H0) continue;
        #pragma unroll
        for (int dx = 0; dx < 2; dx++) {
            int xi = x0 + dx;
            float wx = dx ? wx1 : wx0;
            if (xi < 0 || xi >= W0) continue;
            acc += wy * wx * __ldg(&memb[(size_t)(yi * W0 + xi) * HID + tid]);
        }
    }
    gs[tid] = acc;
    __syncthreads();

    // h1[tid] = tanh(b1[tid] + sum_c gs[c] * w1[c, tid])  (w1 is [in, out])
    float h = b1[tid];
    #pragma unroll 8
    for (int c = 0; c < HID; c++)
        h = fmaf(gs[c], w1[c * HID + tid], h);
    h = tanhf(h);
    h1s[tid] = h;
    __syncthreads();

    // off[k] = b2[k] + sum_j h1[j] * w2[j, k], k = 0..3 -> one warp per k
    int wid = tid >> 5, lane = tid & 31;
    if (wid < 4) {
        float a2 = 0.0f;
        #pragma unroll
        for (int j = lane; j < HID; j += 32)
            a2 += h1s[j] * w2[j * 4 + wid];
        #pragma unroll
        for (int o = 16; o > 0; o >>= 1)
            a2 += __shfl_xor_sync(0xffffffffu, a2, o);
        if (lane == 0)
            g_off[blk * 4 + wid] = S_SCALE_C * tanhf(a2 + b2[wid]);
    }
}

// Kernel 2: per (b,q,s) evaluate the cubic, gather scratch offsets by ref_level, write float4.
__global__ void out_kernel(const float* __restrict__ rp,
                           const int* __restrict__ rl,
                           float* __restrict__ out) {
    int idx = blockIdx.x * blockDim.x + threadIdx.x;   // b*Q*S + q*S + s
    if (idx >= BB * QQ * SNUM) return;
    int s = idx % SNUM;
    int q = (idx / SNUM) % QQ;
    int b = idx / (SNUM * QQ);

    const float* rpq = rp + ((size_t)b * QQ + q) * 8;
    float t  = (float)s * (1.0f / (float)(SNUM - 1));
    float t2 = t * t, t3 = t2 * t;
    float spx = 2.0f * (rpq[0] * t3 + rpq[1] * t2 + rpq[2] * t + rpq[3] - 0.5f);
    float spy = 2.0f * (rpq[4] * t3 + rpq[5] * t2 + rpq[6] * t + rpq[7] - 0.5f);

    int lvl = rl[b * QQ + q];                           // in {0,1,2}
    const float* off = g_off + (((size_t)b * QP + lvl) * SNUM + s) * 4;
    float4 v;
    v.x = off[0] + spx;
    v.y = off[1] + spy;
    v.z = off[2] + spx;
    v.w = off[3] + spy;
    reinterpret_cast<float4*>(out)[idx] = v;
}

extern "C" void kernel_launch(void* const* d_in, const int* in_sizes, int n_in,
                              void* d_out, int out_size) {
    const float* ref_polys = (const float*)d_in[0];
    const float* memory    = (const float*)d_in[1];
    const float* w1        = (const float*)d_in[2];
    const float* b1        = (const float*)d_in[3];
    const float* w2        = (const float*)d_in[4];
    const float* b2        = (const float*)d_in[5];
    const int*   ref_lvls  = (const int*)d_in[6];
    float* out = (float*)d_out;

    sample_mlp_kernel<<<BB * QP * SNUM, HID>>>(ref_polys, memory, w1, b1, w2, b2);

    int total = BB * QQ * SNUM;
    out_kernel<<<(total + 255) / 256, 256>>>(ref_polys, ref_lvls, out);
}